// round 2
// baseline (speedup 1.0000x reference)
#include <cuda_runtime.h>

#define NNODES 8192
#define CDIM   64
#define HBITS  20
#define HSIZE  (1 << HBITS)
#define HMASK  (HSIZE - 1)
#define EMAX   262144

// ---------------- device scratch (no allocations allowed) ----------------
__device__ int   g_hkey[HSIZE];
__device__ int   g_hval[HSIZE];
__device__ float g_deg[NNODES];
__device__ float g_s[NNODES];
__device__ int   g_rcnt[NNODES];
__device__ int   g_rfill[NNODES];
__device__ int   g_rptr[NNODES + 1];
__device__ int   g_ccol[EMAX];
__device__ float g_cw[EMAX];
__device__ float g_t1[NNODES * CDIM];
__device__ float g_t2[NNODES * CDIM];

// ---------------- init ----------------
__global__ void k_init() {
    int i = blockIdx.x * blockDim.x + threadIdx.x;
    if (i < HSIZE) { g_hkey[i] = -1; g_hval[i] = -1; }
    if (i < NNODES) { g_deg[i] = 1.0f; g_rcnt[i] = 0; g_rfill[i] = 0; }
}

// ---------------- hash insert: dedup cells, last edge id wins ----------------
// edge_index is INT32 (JAX x64 disabled => int64 request silently yields int32)
__global__ void k_insert(const int* __restrict__ ei, int E) {
    int e = blockIdx.x * blockDim.x + threadIdx.x;
    if (e >= E) return;
    int row = ei[e];
    int col = ei[E + e];
    int key = (row << 13) | col;
    int slot = (int)(((unsigned)key * 2654435761u) >> (32 - HBITS));
    while (true) {
        int k = g_hkey[slot];
        if (k == key) break;
        if (k == -1) {
            int old = atomicCAS(&g_hkey[slot], -1, key);
            if (old == -1 || old == key) break;
        }
        slot = (slot + 1) & HMASK;
    }
    atomicMax(&g_hval[slot], e);   // last-write-wins semantics
}

// ---------------- degree + per-row count over live slots ----------------
__global__ void k_deg(const float* __restrict__ ew, const float* __restrict__ aw) {
    int i = blockIdx.x * blockDim.x + threadIdx.x;
    if (i >= HSIZE) return;
    int key = g_hkey[i];
    if (key < 0) return;
    int e = g_hval[i];
    float sig = 1.0f / (1.0f + expf(-aw[0]));
    float w = ew[e] * sig;
    int row = key >> 13;
    atomicAdd(&g_deg[row], w);
    atomicAdd(&g_rcnt[row], 1);
}

__global__ void k_rsq() {
    int i = blockIdx.x * blockDim.x + threadIdx.x;
    if (i < NNODES) g_s[i] = rsqrtf(g_deg[i]);   // deg >= 1, never inf
}

// ---------------- exclusive scan of row counts (1 block, 1024 thr x 8) ----------------
__global__ void k_scan() {
    __shared__ int sums[1024];
    int t = threadIdx.x;
    int base = t * 8;
    int local[8];
    int s = 0;
    #pragma unroll
    for (int j = 0; j < 8; j++) { local[j] = s; s += g_rcnt[base + j]; }
    sums[t] = s;
    __syncthreads();
    for (int off = 1; off < 1024; off <<= 1) {
        int v = (t >= off) ? sums[t - off] : 0;
        __syncthreads();
        sums[t] += v;
        __syncthreads();
    }
    int offset = (t == 0) ? 0 : sums[t - 1];
    #pragma unroll
    for (int j = 0; j < 8; j++) g_rptr[base + j] = offset + local[j];
    if (t == 1023) g_rptr[NNODES] = sums[1023];
}

// ---------------- CSR fill with normalized weights ----------------
__global__ void k_fill(const float* __restrict__ ew, const float* __restrict__ aw) {
    int i = blockIdx.x * blockDim.x + threadIdx.x;
    if (i >= HSIZE) return;
    int key = g_hkey[i];
    if (key < 0) return;
    int e = g_hval[i];
    int row = key >> 13;
    int col = key & (NNODES - 1);
    float sig = 1.0f / (1.0f + expf(-aw[0]));
    float w = ew[e] * sig * g_s[row] * g_s[col];
    int pos = g_rptr[row] + atomicAdd(&g_rfill[row], 1);
    g_ccol[pos] = col;
    g_cw[pos] = w;
}

// ---------------- sparse L apply: t1 = L x ----------------
// L x = (1 - s_i^2) x_i - sum_edges w_norm * x_j
__global__ void k_spmv1(const float* __restrict__ x) {
    int row = blockIdx.x;
    int c = threadIdx.x;  // 64 threads
    int start = g_rptr[row], end = g_rptr[row + 1];
    __shared__ int scol[128];
    __shared__ float sw[128];
    float acc = 0.0f;
    for (int b = start; b < end; b += 128) {
        int n = end - b; if (n > 128) n = 128;
        if (c < n)      { scol[c]      = g_ccol[b + c];      sw[c]      = g_cw[b + c]; }
        if (c + 64 < n) { scol[c + 64] = g_ccol[b + c + 64]; sw[c + 64] = g_cw[b + c + 64]; }
        __syncthreads();
        #pragma unroll 4
        for (int j = 0; j < n; j++)
            acc += sw[j] * __ldg(&x[scol[j] * CDIM + c]);
        __syncthreads();
    }
    float si = g_s[row];
    float d = 1.0f - si * si;
    int o = row * CDIM + c;
    g_t1[o] = d * x[o] - acc;
}

// ---------------- t2 = 2 * L t1 - x ----------------
__global__ void k_spmv2(const float* __restrict__ x) {
    int row = blockIdx.x;
    int c = threadIdx.x;
    int start = g_rptr[row], end = g_rptr[row + 1];
    __shared__ int scol[128];
    __shared__ float sw[128];
    float acc = 0.0f;
    for (int b = start; b < end; b += 128) {
        int n = end - b; if (n > 128) n = 128;
        if (c < n)      { scol[c]      = g_ccol[b + c];      sw[c]      = g_cw[b + c]; }
        if (c + 64 < n) { scol[c + 64] = g_ccol[b + c + 64]; sw[c + 64] = g_cw[b + c + 64]; }
        __syncthreads();
        #pragma unroll 4
        for (int j = 0; j < n; j++)
            acc += sw[j] * __ldg(&g_t1[scol[j] * CDIM + c]);
        __syncthreads();
    }
    float si = g_s[row];
    float d = 1.0f - si * si;
    int o = row * CDIM + c;
    g_t2[o] = 2.0f * (d * g_t1[o] - acc) - x[o];
}

// ---------------- epilogue GEMM: out = x W0 + t1 W1 + t2 W2 + b ----------------
__global__ void k_gemm(const float* __restrict__ x, const float* __restrict__ W,
                       const float* __restrict__ bias, float* __restrict__ out) {
    __shared__ float Ws[3 * 64 * 64];   // 48 KB exactly
    for (int i = threadIdx.x; i < 3 * 64 * 64; i += 256) Ws[i] = W[i];
    __syncthreads();
    int c = threadIdx.x & 63;
    int rg = threadIdx.x >> 6;          // 0..3
    int row0 = blockIdx.x * 64 + rg * 16;
    for (int r = row0; r < row0 + 16; r++) {
        const float* xr  = x    + r * 64;
        const float* t1r = g_t1 + r * 64;
        const float* t2r = g_t2 + r * 64;
        float acc = __ldg(&bias[c]);
        #pragma unroll 8
        for (int k = 0; k < 64; k++) {
            acc += __ldg(&xr[k])  * Ws[k * 64 + c];
            acc += __ldg(&t1r[k]) * Ws[4096 + k * 64 + c];
            acc += __ldg(&t2r[k]) * Ws[8192 + k * 64 + c];
        }
        out[r * 64 + c] = acc;
    }
}

// ---------------- launch ----------------
extern "C" void kernel_launch(void* const* d_in, const int* in_sizes, int n_in,
                              void* d_out, int out_size) {
    const float* x    = (const float*)d_in[0];
    const int*   ei   = (const int*)d_in[1];       // int32! (JAX default x64-disabled)
    const float* ew   = (const float*)d_in[2];
    const float* W    = (const float*)d_in[3];
    const float* aw   = (const float*)d_in[4];
    const float* bias = (const float*)d_in[5];
    float* out = (float*)d_out;
    int E = in_sizes[2];

    k_init  <<<HSIZE / 256, 256>>>();
    k_insert<<<(E + 255) / 256, 256>>>(ei, E);
    k_deg   <<<HSIZE / 256, 256>>>(ew, aw);
    k_rsq   <<<NNODES / 256, 256>>>();
    k_scan  <<<1, 1024>>>();
    k_fill  <<<HSIZE / 256, 256>>>(ew, aw);
    k_spmv1 <<<NNODES, 64>>>(x);
    k_spmv2 <<<NNODES, 64>>>(x);
    k_gemm  <<<NNODES / 64, 256>>>(x, W, bias, out);
}